// round 1
// baseline (speedup 1.0000x reference)
#include <cuda_runtime.h>
#include <math.h>

// ---------------- problem constants ----------------
#define BB     8
#define NTOK   1024
#define DD     256
#define LL     4
#define MFF    1024
#define HH     8
#define DHEAD  32
#define NT     (BB*NTOK)      // 8192 tokens
#define KC     64             // clusters
#define KM_IT  10

// ---------------- scratch (static device globals; no allocation allowed) ----
__device__ float g_x   [NT*DD];        // running residual stream
__device__ float g_xn  [NT*DD];        // layernorm output
__device__ float g_q   [NT*DD];        // q projection
__device__ float g_kv  [NT*2*DD];      // k|v projection
__device__ float g_ao  [NT*DD];        // attention output
__device__ float g_hh  [NT*MFF];       // ffn hidden
__device__ float g_xsq [NT];           // per-point |x|^2
__device__ float g_cent[KC*DD];        // kmeans centers
__device__ float g_csq [KC];           // per-center |c|^2
__device__ float g_csum[KC*DD];        // segment sums
__device__ float g_ccnt[KC];           // segment counts
__device__ int   g_lab [NT];           // labels
__device__ float g_cpro[KC*DD];        // centers @ kW + kb

// ---------------- small helpers ----------------
__device__ __forceinline__ float gelu_f(float x) {
    return 0.5f * x * (1.0f + erff(x * 0.7071067811865476f));
}

// block (256 threads) reduce-sum; result broadcast to all threads via smem
__device__ __forceinline__ float blockSum256(float v) {
    __shared__ float red[8];
    int t = threadIdx.x;
    #pragma unroll
    for (int o = 16; o > 0; o >>= 1) v += __shfl_xor_sync(0xffffffffu, v, o);
    if ((t & 31) == 0) red[t >> 5] = v;
    __syncthreads();
    float s = 0.f;
    if (t == 0) {
        #pragma unroll
        for (int i = 0; i < 8; i++) s += red[i];
        red[0] = s;
    }
    __syncthreads();
    s = red[0];
    __syncthreads();
    return s;
}

// ---------------- elementwise copy ----------------
__global__ void copy_kernel(const float* __restrict__ src, float* __restrict__ dst, int n) {
    int i = blockIdx.x * blockDim.x + threadIdx.x;
    if (i < n) dst[i] = src[i];
}

// ---------------- layernorm: one block (256 thr) per row of 256 ----------------
__global__ void ln_kernel(const float* __restrict__ x, const float* __restrict__ g,
                          const float* __restrict__ b, float* __restrict__ out) {
    int row = blockIdx.x;
    int t = threadIdx.x;
    float v = x[(size_t)row * DD + t];
    float mean = blockSum256(v) * (1.0f / DD);
    float d = v - mean;
    float var = blockSum256(d * d) * (1.0f / DD);
    out[(size_t)row * DD + t] = d * rsqrtf(var + 1e-5f) * g[t] + b[t];
}

// ---------------- row sum-of-squares (rows of 256) ----------------
__global__ void rowsumsq_kernel(const float* __restrict__ x, float* __restrict__ out) {
    int row = blockIdx.x;
    int t = threadIdx.x;
    float v = x[(size_t)row * DD + t];
    float s = blockSum256(v * v);
    if (t == 0) out[row] = s;
}

// ---------------- fp32 tiled GEMM: C = A[MxK] @ B[KxN] (+bias)(+gelu)(+res) ---
// BM=BN=128, BK=8, 256 threads, 8x8 microtile. N must be multiple of 128,
// K multiple of 8; M arbitrary (guarded).
__global__ __launch_bounds__(256)
void gemm_kernel(const float* __restrict__ A, const float* __restrict__ Bm,
                 const float* __restrict__ bias, const float* __restrict__ res,
                 float* __restrict__ C, int M, int N, int K, int act) {
    __shared__ float As[8][128];
    __shared__ float Bs[8][128];
    const int m0 = blockIdx.y * 128;
    const int n0 = blockIdx.x * 128;
    const int t  = threadIdx.x;
    const int tx = t & 15;        // 0..15 -> 8 cols each
    const int ty = t >> 4;        // 0..15 -> 8 rows each

    float acc[8][8];
    #pragma unroll
    for (int i = 0; i < 8; i++)
        #pragma unroll
        for (int j = 0; j < 8; j++) acc[i][j] = 0.f;

    const int arow = t >> 1, aseg = t & 1;          // A: 128 rows x 8 cols
    const int brow = t >> 5, bcol = (t & 31) * 4;   // B: 8 rows x 128 cols

    for (int k0 = 0; k0 < K; k0 += 8) {
        float4 av = make_float4(0.f, 0.f, 0.f, 0.f);
        if (m0 + arow < M)
            av = *(const float4*)&A[(size_t)(m0 + arow) * K + k0 + aseg * 4];
        As[aseg * 4 + 0][arow] = av.x;
        As[aseg * 4 + 1][arow] = av.y;
        As[aseg * 4 + 2][arow] = av.z;
        As[aseg * 4 + 3][arow] = av.w;
        float4 bv = *(const float4*)&Bm[(size_t)(k0 + brow) * N + n0 + bcol];
        *(float4*)&Bs[brow][bcol] = bv;
        __syncthreads();

        #pragma unroll
        for (int kk = 0; kk < 8; kk++) {
            float a[8], bb[8];
            *(float4*)&a[0]  = *(const float4*)&As[kk][ty * 8];
            *(float4*)&a[4]  = *(const float4*)&As[kk][ty * 8 + 4];
            *(float4*)&bb[0] = *(const float4*)&Bs[kk][tx * 8];
            *(float4*)&bb[4] = *(const float4*)&Bs[kk][tx * 8 + 4];
            #pragma unroll
            for (int i = 0; i < 8; i++)
                #pragma unroll
                for (int j = 0; j < 8; j++) acc[i][j] += a[i] * bb[j];
        }
        __syncthreads();
    }

    #pragma unroll
    for (int i = 0; i < 8; i++) {
        int row = m0 + ty * 8 + i;
        if (row < M) {
            size_t base = (size_t)row * N;
            #pragma unroll
            for (int j = 0; j < 8; j++) {
                int col = n0 + tx * 8 + j;
                float v = acc[i][j];
                if (bias) v += bias[col];
                if (act == 1) v = gelu_f(v);
                if (res) v += res[base + col];
                C[base + col] = v;
            }
        }
    }
}

// ---------------- flash attention: grid(16 qtiles, 8 heads, 8 batch) ----------
// 64 threads; each thread owns one q row (dh=32 in registers), online softmax.
__global__ __launch_bounds__(64)
void attn_kernel(const float* __restrict__ q, const float* __restrict__ kv,
                 float* __restrict__ out) {
    __shared__ float Ks[64][32];
    __shared__ float Vs[64][32];
    __shared__ float Ss[64][65];   // padded: no bank conflicts
    const int qt = blockIdx.x, h = blockIdx.y, b = blockIdx.z;
    const int t = threadIdx.x;
    const float scale = 0.17677669529663687f;  // 1/sqrt(32)

    const int qrow = qt * 64 + t;
    const float* qp = q + ((size_t)(b * NTOK) + qrow) * DD + h * DHEAD;
    float qr[32];
    #pragma unroll
    for (int d = 0; d < 32; d++) qr[d] = qp[d] * scale;

    float o[32];
    #pragma unroll
    for (int d = 0; d < 32; d++) o[d] = 0.f;
    float m = -1e30f, l = 0.f;

    for (int kt = 0; kt < NTOK; kt += 64) {
        const float* kbase = kv + ((size_t)(b * NTOK) + kt) * (2 * DD) + h * DHEAD;
        #pragma unroll
        for (int i = 0; i < 8; i++) {
            int idx = i * 64 + t;              // float4 index 0..511
            int r = idx >> 3, c4 = (idx & 7) * 4;
            *(float4*)&Ks[r][c4] = *(const float4*)&kbase[(size_t)r * (2 * DD) + c4];
            *(float4*)&Vs[r][c4] = *(const float4*)&kbase[(size_t)r * (2 * DD) + DD + c4];
        }
        __syncthreads();

        float tmax = -1e30f;
        #pragma unroll 4
        for (int j = 0; j < 64; j++) {
            float s = 0.f;
            #pragma unroll
            for (int d = 0; d < 32; d++) s += qr[d] * Ks[j][d];
            Ss[t][j] = s;
            tmax = fmaxf(tmax, s);
        }
        float mnew = fmaxf(m, tmax);
        float corr = __expf(m - mnew);
        l *= corr;
        #pragma unroll
        for (int d = 0; d < 32; d++) o[d] *= corr;
        #pragma unroll 2
        for (int j = 0; j < 64; j++) {
            float p = __expf(Ss[t][j] - mnew);
            l += p;
            #pragma unroll
            for (int d = 0; d < 32; d++) o[d] += p * Vs[j][d];
        }
        m = mnew;
        __syncthreads();
    }

    float inv = 1.f / l;
    float* op = out + ((size_t)(b * NTOK) + qrow) * DD + h * DHEAD;
    #pragma unroll
    for (int d = 0; d < 32; d++) op[d] = o[d] * inv;
}

// ---------------- kmeans: init centers from first 64 rows ----------------
__global__ void initcent_kernel(const float* __restrict__ x, float* __restrict__ cent) {
    cent[(size_t)blockIdx.x * DD + threadIdx.x] = x[(size_t)blockIdx.x * DD + threadIdx.x];
}

// ---------------- kmeans assign: 128 points/block, 64 centers in registers ----
__global__ __launch_bounds__(128)
void assign_kernel(const float* __restrict__ x, const float* __restrict__ cent,
                   const float* __restrict__ xsq, const float* __restrict__ csq,
                   int* __restrict__ lab) {
    __shared__ float Xs[128][33];   // padded
    __shared__ float Cs[64][32];
    const int t = threadIdx.x;
    const int p0 = blockIdx.x * 128;

    float dot[64];
    #pragma unroll
    for (int c = 0; c < 64; c++) dot[c] = 0.f;

    for (int dc = 0; dc < DD; dc += 32) {
        #pragma unroll
        for (int i = 0; i < 8; i++) {               // 1024 float4 / 128 thr
            int idx = i * 128 + t;
            int r = idx >> 3, c4 = (idx & 7) * 4;
            float4 v = *(const float4*)&x[(size_t)(p0 + r) * DD + dc + c4];
            Xs[r][c4 + 0] = v.x; Xs[r][c4 + 1] = v.y;
            Xs[r][c4 + 2] = v.z; Xs[r][c4 + 3] = v.w;
        }
        #pragma unroll
        for (int i = 0; i < 4; i++) {               // 512 float4 / 128 thr
            int idx = i * 128 + t;
            int r = idx >> 3, c4 = (idx & 7) * 4;
            *(float4*)&Cs[r][c4] = *(const float4*)&cent[(size_t)r * DD + dc + c4];
        }
        __syncthreads();
        #pragma unroll 4
        for (int d = 0; d < 32; d++) {
            float xv = Xs[t][d];
            #pragma unroll
            for (int c = 0; c < 64; c++) dot[c] += xv * Cs[c][d];
        }
        __syncthreads();
    }

    float xs = xsq[p0 + t];
    float best = 3.4e38f;
    int bl = 0;
    #pragma unroll
    for (int c = 0; c < 64; c++) {
        float dd = xs - 2.f * dot[c] + csq[c];
        if (dd < best) { best = dd; bl = c; }   // strict < keeps first index (argmin)
    }
    lab[p0 + t] = bl;
}

// ---------------- deterministic segment sum: one block per center -------------
__global__ __launch_bounds__(256)
void segsum_kernel(const float* __restrict__ x, const int* __restrict__ lab,
                   float* __restrict__ sums, float* __restrict__ cnts) {
    const int c = blockIdx.x;
    const int t = threadIdx.x;
    __shared__ int labs[256];
    float acc = 0.f;
    int cnt = 0;
    for (int p0 = 0; p0 < NT; p0 += 256) {
        labs[t] = lab[p0 + t];
        __syncthreads();
        #pragma unroll 8
        for (int i = 0; i < 256; i++) {
            if (labs[i] == c) { acc += x[(size_t)(p0 + i) * DD + t]; cnt++; }
        }
        __syncthreads();
    }
    sums[(size_t)c * DD + t] = acc;
    if (t == 0) cnts[c] = (float)cnt;
}

__global__ void update_kernel(float* __restrict__ cent, const float* __restrict__ sums,
                              const float* __restrict__ cnts) {
    int c = blockIdx.x, t = threadIdx.x;
    float cnt = cnts[c];
    if (cnt > 0.f) cent[(size_t)c * DD + t] = sums[(size_t)c * DD + t] / fmaxf(cnt, 1.f);
}

__global__ void gather_kernel(const float* __restrict__ cproj, const int* __restrict__ lab,
                              float* __restrict__ out) {
    int p = blockIdx.x, t = threadIdx.x;
    out[(size_t)p * DD + t] = cproj[(size_t)lab[p] * DD + t];
}

// ---------------- host orchestration ----------------
extern "C" void kernel_launch(void* const* d_in, const int* in_sizes, int n_in,
                              void* d_out, int out_size) {
    const float* x_in = (const float*)d_in[0];
    const float* ln1g = (const float*)d_in[1];
    const float* ln1b = (const float*)d_in[2];
    const float* Wq   = (const float*)d_in[3];
    const float* Wkv  = (const float*)d_in[4];
    const float* Wo   = (const float*)d_in[5];
    const float* bo   = (const float*)d_in[6];
    const float* ln2g = (const float*)d_in[7];
    const float* ln2b = (const float*)d_in[8];
    const float* W1   = (const float*)d_in[9];
    const float* b1   = (const float*)d_in[10];
    const float* W2   = (const float*)d_in[11];
    const float* b2   = (const float*)d_in[12];
    const float* kW   = (const float*)d_in[13];
    const float* kb   = (const float*)d_in[14];
    float* out = (float*)d_out;

    float *p_x, *p_xn, *p_q, *p_kv, *p_ao, *p_h, *p_xsq, *p_cent, *p_csq, *p_csum, *p_ccnt, *p_cpro;
    int *p_lab;
    cudaGetSymbolAddress((void**)&p_x,    g_x);
    cudaGetSymbolAddress((void**)&p_xn,   g_xn);
    cudaGetSymbolAddress((void**)&p_q,    g_q);
    cudaGetSymbolAddress((void**)&p_kv,   g_kv);
    cudaGetSymbolAddress((void**)&p_ao,   g_ao);
    cudaGetSymbolAddress((void**)&p_h,    g_hh);
    cudaGetSymbolAddress((void**)&p_xsq,  g_xsq);
    cudaGetSymbolAddress((void**)&p_cent, g_cent);
    cudaGetSymbolAddress((void**)&p_csq,  g_csq);
    cudaGetSymbolAddress((void**)&p_csum, g_csum);
    cudaGetSymbolAddress((void**)&p_ccnt, g_ccnt);
    cudaGetSymbolAddress((void**)&p_lab,  g_lab);
    cudaGetSymbolAddress((void**)&p_cpro, g_cpro);

    // x -> residual stream
    copy_kernel<<<(NT * DD + 255) / 256, 256>>>(x_in, p_x, NT * DD);

    for (int l = 0; l < LL; l++) {
        const float* wq  = Wq  + (size_t)l * DD * DD;
        const float* wkv = Wkv + (size_t)l * DD * (2 * DD);
        const float* wo  = Wo  + (size_t)l * DD * DD;
        const float* w1  = W1  + (size_t)l * DD * MFF;
        const float* w2  = W2  + (size_t)l * MFF * DD;

        // ln1
        ln_kernel<<<NT, 256>>>(p_x, ln1g + l * DD, ln1b + l * DD, p_xn);
        // q, kv projections
        gemm_kernel<<<dim3(DD / 128, NT / 128), 256>>>(p_xn, wq,  nullptr, nullptr, p_q,  NT, DD,     DD, 0);
        gemm_kernel<<<dim3(2 * DD / 128, NT / 128), 256>>>(p_xn, wkv, nullptr, nullptr, p_kv, NT, 2 * DD, DD, 0);
        // attention
        attn_kernel<<<dim3(NTOK / 64, HH, BB), 64>>>(p_q, p_kv, p_ao);
        // out proj + bias + residual (in place into x)
        gemm_kernel<<<dim3(DD / 128, NT / 128), 256>>>(p_ao, wo, bo + l * DD, p_x, p_x, NT, DD, DD, 0);
        // ln2
        ln_kernel<<<NT, 256>>>(p_x, ln2g + l * DD, ln2b + l * DD, p_xn);
        // ffn up + gelu
        gemm_kernel<<<dim3(MFF / 128, NT / 128), 256>>>(p_xn, w1, b1 + l * MFF, nullptr, p_h, NT, MFF, DD, 1);
        // ffn down + bias + residual
        gemm_kernel<<<dim3(DD / 128, NT / 128), 256>>>(p_h, w2, b2 + l * DD, p_x, p_x, NT, DD, MFF, 0);
    }

    // ---- kmeans ----
    initcent_kernel<<<KC, 256>>>(p_x, p_cent);
    rowsumsq_kernel<<<NT, 256>>>(p_x, p_xsq);

    for (int it = 0; it < KM_IT; it++) {
        rowsumsq_kernel<<<KC, 256>>>(p_cent, p_csq);
        assign_kernel<<<NT / 128, 128>>>(p_x, p_cent, p_xsq, p_csq, p_lab);
        segsum_kernel<<<KC, 256>>>(p_x, p_lab, p_csum, p_ccnt);
        update_kernel<<<KC, 256>>>(p_cent, p_csum, p_ccnt);
    }
    // final assignment
    rowsumsq_kernel<<<KC, 256>>>(p_cent, p_csq);
    assign_kernel<<<NT / 128, 128>>>(p_x, p_cent, p_xsq, p_csq, p_lab);

    // project centers once (centers[labels] @ kW == (centers @ kW)[labels])
    gemm_kernel<<<dim3(DD / 128, 1), 256>>>(p_cent, kW, kb, nullptr, p_cpro, KC, DD, DD, 0);
    gather_kernel<<<NT, 256>>>(p_cpro, p_lab, out);
}